// round 3
// baseline (speedup 1.0000x reference)
#include <cuda_runtime.h>
#include <cuda_bf16.h>

#define BB 16
#define LL 2048
#define DD 1024
#define SS 32
#define NUM_BUCKETS 64
#define WIDTH_BUCKET 16
#define LEN_BUCKET 32
#define NUM_LABELS 3
#define ROWF (DD / 4)          // float4 per row = 256
#define CROWS 8                // rows per chunk
#define CHUNKS 8               // chunks per span (covers cnt <= 64)
#define NSPAN (BB * SS)        // 512
#define NBLK (NSPAN * CHUNKS)  // 4096

// Deterministic chunk partials (always fully overwritten each run — no reset needed)
__device__ float g_part[NSPAN * CHUNKS * 3];
__device__ int   g_len[BB];
__device__ unsigned g_done = 0;   // reset by final block each run

__global__ void __launch_bounds__(256, 4)
k_fused(const float* __restrict__ enc,
        const int*   __restrict__ mask,
        const int*   __restrict__ heads,
        const int*   __restrict__ tails,
        const int*   __restrict__ labels,
        const float* __restrict__ wemb,
        const float* __restrict__ lemb,
        const float* __restrict__ clsw,   // [DD+16, 3]
        const float* __restrict__ clsb,   // [3]
        float*       __restrict__ out)    // logits [512*3] then loss [1]
{
    const int unit  = blockIdx.x;        // 0..4095
    const int span  = unit >> 3;         // 0..511
    const int chunk = unit & (CHUNKS - 1);
    const int b     = span >> 5;
    const int t     = threadIdx.x;       // 256 threads; thread t owns float4 lane t

    const int head  = heads[span];
    const int tail  = tails[span];
    const int start = head + 1;
    const int cnt   = tail - start;
    const int r0    = start + chunk * CROWS;
    const int r1    = min(r0 + CROWS, tail);

    // ---- stream this chunk's rows (predicated full unroll -> MLP up to 8) ----
    const float4* p = (const float4*)enc + (size_t)b * LL * ROWF
                      + (size_t)r0 * ROWF + t;
    float4 acc = make_float4(0.f, 0.f, 0.f, 0.f);
    #pragma unroll
    for (int i = 0; i < CROWS; ++i) {
        if (r0 + i < r1) {
            float4 v = __ldcs(p + (size_t)i * ROWF);
            acc.x += v.x; acc.y += v.y; acc.z += v.z; acc.w += v.w;
        }
    }
    const float inv = 1.0f / (float)max(cnt, 1);
    acc.x *= inv; acc.y *= inv; acc.z *= inv; acc.w *= inv;

    // ---- fold this thread's 4 dims into 3 partial logits (coalesced clsw reads) ----
    float p0, p1, p2;
    {
        const float* w = clsw + (size_t)(t * 4) * 3;
        p0 = acc.x * w[0] + acc.y * w[3] + acc.z * w[6] + acc.w * w[9];
        p1 = acc.x * w[1] + acc.y * w[4] + acc.z * w[7] + acc.w * w[10];
        p2 = acc.x * w[2] + acc.y * w[5] + acc.z * w[8] + acc.w * w[11];
    }

    // ---- designated blocks also compute mask length for one example ----
    int msum = 0;
    if (unit < BB) {
        const int* mrow = mask + (size_t)unit * LL;
        #pragma unroll
        for (int i = 0; i < LL / 256; ++i) msum += mrow[t + i * 256];
    }

    // ---- block reduction of (p0, p1, p2, msum) ----
    #pragma unroll
    for (int o = 16; o; o >>= 1) {
        p0   += __shfl_down_sync(0xffffffffu, p0, o);
        p1   += __shfl_down_sync(0xffffffffu, p1, o);
        p2   += __shfl_down_sync(0xffffffffu, p2, o);
        msum += __shfl_down_sync(0xffffffffu, msum, o);
    }
    __shared__ float sred[8][3];
    __shared__ int   smsk[8];
    if ((t & 31) == 0) {
        sred[t >> 5][0] = p0; sred[t >> 5][1] = p1; sred[t >> 5][2] = p2;
        smsk[t >> 5] = msum;
    }
    __syncthreads();
    if (t == 0) {
        float l0 = 0.f, l1 = 0.f, l2 = 0.f; int len = 0;
        #pragma unroll
        for (int w = 0; w < 8; ++w) {
            l0 += sred[w][0]; l1 += sred[w][1]; l2 += sred[w][2]; len += smsk[w];
        }
        float* gp = g_part + (size_t)(span * CHUNKS + chunk) * 3;
        gp[0] = l0; gp[1] = l1; gp[2] = l2;
        if (unit < BB) g_len[unit] = len;
    }

    // ---- last-block-done: finalize logits + CE in-kernel ----
    __threadfence();
    __shared__ int s_last;
    if (t == 0) s_last = (atomicAdd(&g_done, 1u) == (unsigned)(NBLK - 1));
    __syncthreads();
    if (!s_last) return;
    if (t == 0) g_done = 0;   // reset for next graph replay
    __threadfence();          // acquire: all blocks' partials visible

    float nll = 0.f;
    int valid = 0;
    #pragma unroll
    for (int k = 0; k < 2; ++k) {
        const int sp = t + k * 256;       // 0..511
        const int eb = sp >> 5;

        float l0 = 0.f, l1 = 0.f, l2 = 0.f;
        const float* gp = g_part + (size_t)sp * CHUNKS * 3;
        #pragma unroll
        for (int c = 0; c < CHUNKS; ++c) {
            l0 += gp[c * 3 + 0]; l1 += gp[c * 3 + 1]; l2 += gp[c * 3 + 2];
        }

        const int hh = heads[sp];
        const int tt = tails[sp];
        int wb = (tt - hh) / WIDTH_BUCKET;
        wb = min(max(wb, 0), NUM_BUCKETS - 1);
        int lb = g_len[eb] / LEN_BUCKET;
        lb = min(max(lb, 0), NUM_BUCKETS - 1);

        float e0 = clsb[0], e1 = clsb[1], e2 = clsb[2];
        #pragma unroll
        for (int j = 0; j < 8; ++j) {
            const float wv = wemb[wb * 8 + j];
            const float lv = lemb[lb * 8 + j];
            const float* cw = clsw + (size_t)(DD + j) * 3;
            const float* cl = clsw + (size_t)(DD + 8 + j) * 3;
            e0 += wv * cw[0] + lv * cl[0];
            e1 += wv * cw[1] + lv * cl[1];
            e2 += wv * cw[2] + lv * cl[2];
        }
        const float a = l0 + e0, bb2 = l1 + e1, cc = l2 + e2;
        float* o = out + (size_t)sp * 3;
        o[0] = a; o[1] = bb2; o[2] = cc;

        // CE directly from registers
        const float m = fmaxf(a, fmaxf(bb2, cc));
        const float lse = m + logf(expf(a - m) + expf(bb2 - m) + expf(cc - m));
        const int lab = labels[sp];
        if (lab > -1) {
            valid += 1;
            const int cl2 = max(lab, 0);
            const float x = (cl2 == 0) ? a : ((cl2 == 1) ? bb2 : cc);
            nll += lse - x;
        }
    }
    #pragma unroll
    for (int o = 16; o; o >>= 1) {
        nll   += __shfl_down_sync(0xffffffffu, nll, o);
        valid += __shfl_down_sync(0xffffffffu, valid, o);
    }
    __shared__ float snll[8];
    __shared__ int   svld[8];
    if ((t & 31) == 0) { snll[t >> 5] = nll; svld[t >> 5] = valid; }
    __syncthreads();
    if (t == 0) {
        float tn = 0.f; int tv = 0;
        #pragma unroll
        for (int w = 0; w < 8; ++w) { tn += snll[w]; tv += svld[w]; }
        out[NSPAN * NUM_LABELS] = tn / (float)max(tv, 1);
    }
}

extern "C" void kernel_launch(void* const* d_in, const int* in_sizes, int n_in,
                              void* d_out, int out_size)
{
    const float* enc   = (const float*)d_in[0];  // [16,2048,1024] f32
    const int*   mask  = (const int*)  d_in[1];  // [16,2048] i32
    const int*   heads = (const int*)  d_in[2];  // [16,32] i32
    const int*   tails = (const int*)  d_in[3];  // [16,32] i32
    const int*   labs  = (const int*)  d_in[4];  // [16,32] i32
    const float* wemb  = (const float*)d_in[5];  // [64,8] f32
    const float* lemb  = (const float*)d_in[6];  // [64,8] f32
    const float* clsw  = (const float*)d_in[7];  // [1040,3] f32
    const float* clsb  = (const float*)d_in[8];  // [3] f32

    k_fused<<<NBLK, 256>>>(enc, mask, heads, tails, labs,
                           wemb, lemb, clsw, clsb, (float*)d_out);
}

// round 4
// speedup vs baseline: 1.3531x; 1.3531x over previous
#include <cuda_runtime.h>
#include <cuda_bf16.h>

#define BB 16
#define LL 2048
#define DD 1024
#define SS 32
#define NUM_BUCKETS 64
#define WIDTH_BUCKET 16
#define LEN_BUCKET 32
#define NUM_LABELS 3
#define ROWF (DD / 4)          // float4 per row = 256
#define HALVES 2               // D-split factor
#define HROWF (ROWF / HALVES)  // float4 lanes per half = 128
#define NSPAN (BB * SS)        // 512
#define NBLK (NSPAN * HALVES)  // 1024 CTAs, single wave at occ>=7

// Deterministic per-half partial logits (fully overwritten each run)
__device__ float g_part[NSPAN * HALVES * 3];
__device__ int   g_len[BB];
__device__ unsigned g_done = 0;   // reset by final block each run

__global__ void __launch_bounds__(128, 8)
k_fused(const float* __restrict__ enc,
        const int*   __restrict__ mask,
        const int*   __restrict__ heads,
        const int*   __restrict__ tails,
        const int*   __restrict__ labels,
        const float* __restrict__ wemb,
        const float* __restrict__ lemb,
        const float* __restrict__ clsw,   // [DD+16, 3]
        const float* __restrict__ clsb,   // [3]
        float*       __restrict__ out)    // logits [512*3] then loss [1]
{
    const int blk  = blockIdx.x;         // 0..1023
    const int span = blk >> 1;           // 0..511
    const int half = blk & 1;
    const int b    = span >> 5;
    const int t    = threadIdx.x;        // 128 threads

    const int head  = heads[span];
    const int tail  = tails[span];
    const int start = head + 1;
    const int cnt   = tail - start;

    // thread owns float4 lane (half*128 + t) of each row
    const int lane = half * HROWF + t;
    const float4* p = (const float4*)enc + (size_t)b * LL * ROWF
                      + (size_t)start * ROWF + lane;
    float4 acc = make_float4(0.f, 0.f, 0.f, 0.f);

    if (cnt == 63) {
        #pragma unroll 7
        for (int i = 0; i < 63; ++i) {
            float4 v = __ldcs(p + (size_t)i * ROWF);
            acc.x += v.x; acc.y += v.y; acc.z += v.z; acc.w += v.w;
        }
    } else {
        #pragma unroll 4
        for (int i = 0; i < cnt; ++i) {
            float4 v = __ldcs(p + (size_t)i * ROWF);
            acc.x += v.x; acc.y += v.y; acc.z += v.z; acc.w += v.w;
        }
    }
    const float inv = 1.0f / (float)max(cnt, 1);
    acc.x *= inv; acc.y *= inv; acc.z *= inv; acc.w *= inv;

    // ---- fold this thread's 4 dims into 3 partial logits ----
    float p0, p1, p2;
    {
        const float* w = clsw + (size_t)(lane * 4) * 3;  // coalesced across threads
        p0 = acc.x * w[0] + acc.y * w[3] + acc.z * w[6] + acc.w * w[9];
        p1 = acc.x * w[1] + acc.y * w[4] + acc.z * w[7] + acc.w * w[10];
        p2 = acc.x * w[2] + acc.y * w[5] + acc.z * w[8] + acc.w * w[11];
    }

    // ---- 16 designated blocks also compute mask length for one example ----
    int msum = 0;
    const bool do_mask = (half == 1) && ((span & (SS - 1)) == 0);
    if (do_mask) {
        const int* mrow = mask + (size_t)b * LL;
        #pragma unroll
        for (int i = 0; i < LL / 128; ++i) msum += mrow[t + i * 128];
    }

    // ---- block reduction over 128 threads (4 warps) ----
    #pragma unroll
    for (int o = 16; o; o >>= 1) {
        p0   += __shfl_down_sync(0xffffffffu, p0, o);
        p1   += __shfl_down_sync(0xffffffffu, p1, o);
        p2   += __shfl_down_sync(0xffffffffu, p2, o);
        msum += __shfl_down_sync(0xffffffffu, msum, o);
    }
    __shared__ float sred[4][3];
    __shared__ int   smsk[4];
    if ((t & 31) == 0) {
        sred[t >> 5][0] = p0; sred[t >> 5][1] = p1; sred[t >> 5][2] = p2;
        smsk[t >> 5] = msum;
    }
    __syncthreads();
    if (t == 0) {
        float l0 = 0.f, l1 = 0.f, l2 = 0.f; int len = 0;
        #pragma unroll
        for (int w = 0; w < 4; ++w) {
            l0 += sred[w][0]; l1 += sred[w][1]; l2 += sred[w][2]; len += smsk[w];
        }
        float* gp = g_part + (size_t)blk * 3;
        gp[0] = l0; gp[1] = l1; gp[2] = l2;
        if (do_mask) g_len[b] = len;
    }

    // ---- last-block-done: finalize logits + CE ----
    __threadfence();
    __shared__ int s_last;
    if (t == 0) s_last = (atomicAdd(&g_done, 1u) == (unsigned)(NBLK - 1));
    __syncthreads();
    if (!s_last) return;
    if (t == 0) g_done = 0;   // reset for next graph replay
    __threadfence();          // acquire: all blocks' partials visible

    float nll = 0.f;
    int valid = 0;
    #pragma unroll
    for (int k = 0; k < 4; ++k) {
        const int sp = t + k * 128;       // 0..511
        const int eb = sp >> 5;

        const float* gp = g_part + (size_t)sp * HALVES * 3;
        float l0 = gp[0] + gp[3];
        float l1 = gp[1] + gp[4];
        float l2 = gp[2] + gp[5];

        const int hh = heads[sp];
        const int tt = tails[sp];
        int wb = (tt - hh) / WIDTH_BUCKET;
        wb = min(max(wb, 0), NUM_BUCKETS - 1);
        int lb = g_len[eb] / LEN_BUCKET;
        lb = min(max(lb, 0), NUM_BUCKETS - 1);

        float e0 = clsb[0], e1 = clsb[1], e2 = clsb[2];
        #pragma unroll
        for (int j = 0; j < 8; ++j) {
            const float wv = wemb[wb * 8 + j];
            const float lv = lemb[lb * 8 + j];
            const float* cw = clsw + (size_t)(DD + j) * 3;
            const float* cl = clsw + (size_t)(DD + 8 + j) * 3;
            e0 += wv * cw[0] + lv * cl[0];
            e1 += wv * cw[1] + lv * cl[1];
            e2 += wv * cw[2] + lv * cl[2];
        }
        const float a = l0 + e0, b2 = l1 + e1, c = l2 + e2;
        float* o = out + (size_t)sp * 3;
        o[0] = a; o[1] = b2; o[2] = c;

        const float m = fmaxf(a, fmaxf(b2, c));
        const float lse = m + logf(expf(a - m) + expf(b2 - m) + expf(c - m));
        const int lab = labels[sp];
        if (lab > -1) {
            valid += 1;
            const int cl2 = max(lab, 0);
            const float x = (cl2 == 0) ? a : ((cl2 == 1) ? b2 : c);
            nll += lse - x;
        }
    }
    #pragma unroll
    for (int o = 16; o; o >>= 1) {
        nll   += __shfl_down_sync(0xffffffffu, nll, o);
        valid += __shfl_down_sync(0xffffffffu, valid, o);
    }
    __shared__ float snll[4];
    __shared__ int   svld[4];
    if ((t & 31) == 0) { snll[t >> 5] = nll; svld[t >> 5] = valid; }
    __syncthreads();
    if (t == 0) {
        float tn = 0.f; int tv = 0;
        #pragma unroll
        for (int w = 0; w < 4; ++w) { tn += snll[w]; tv += svld[w]; }
        out[NSPAN * NUM_LABELS] = tn / (float)max(tv, 1);
    }
}

extern "C" void kernel_launch(void* const* d_in, const int* in_sizes, int n_in,
                              void* d_out, int out_size)
{
    const float* enc   = (const float*)d_in[0];  // [16,2048,1024] f32
    const int*   mask  = (const int*)  d_in[1];  // [16,2048] i32
    const int*   heads = (const int*)  d_in[2];  // [16,32] i32
    const int*   tails = (const int*)  d_in[3];  // [16,32] i32
    const int*   labs  = (const int*)  d_in[4];  // [16,32] i32
    const float* wemb  = (const float*)d_in[5];  // [64,8] f32
    const float* lemb  = (const float*)d_in[6];  // [64,8] f32
    const float* clsw  = (const float*)d_in[7];  // [1040,3] f32
    const float* clsb  = (const float*)d_in[8];  // [3] f32

    k_fused<<<NBLK, 128>>>(enc, mask, heads, tails, labs,
                           wemb, lemb, clsw, clsb, (float*)d_out);
}

// round 5
// speedup vs baseline: 1.4620x; 1.0804x over previous
#include <cuda_runtime.h>
#include <cuda_bf16.h>
#include <cstdint>

#define BB 16
#define LL 2048
#define DD 1024
#define SS 32
#define NUM_BUCKETS 64
#define WIDTH_BUCKET 16
#define LEN_BUCKET 32
#define NUM_LABELS 3
#define ROWF (DD / 4)           // float4 per row = 256
#define ROWB (DD * 4)           // bytes per row = 4096
#define NSPAN (BB * SS)         // 512
#define NS 2                    // pipeline stages
#define TROWS 4                 // rows per TMA tile
#define TBYTES (TROWS * ROWB)   // 16384

__device__ unsigned g_done = 0;   // reset by final block each run (graph-replay safe)

// ---- inline PTX helpers (no external includes) ----
__device__ __forceinline__ uint32_t smem_u32(const void* p) {
    uint32_t a;
    asm("{ .reg .u64 t; cvta.to.shared.u64 t, %1; cvt.u32.u64 %0, t; }"
        : "=r"(a) : "l"(p));
    return a;
}
#define MBAR_INIT(addr, cnt) \
    asm volatile("mbarrier.init.shared.b64 [%0], %1;" :: "r"(addr), "r"(cnt) : "memory")
#define MBAR_EXPECT_TX(addr, bytes) \
    asm volatile("mbarrier.arrive.expect_tx.shared.b64 _, [%0], %1;" \
                 :: "r"(addr), "r"(bytes) : "memory")
#define BULK_G2S(dst, src, bytes, mbar) \
    asm volatile("cp.async.bulk.shared::cluster.global.mbarrier::complete_tx::bytes " \
                 "[%0], [%1], %2, [%3];" \
                 :: "r"(dst), "l"(src), "r"(bytes), "r"(mbar) : "memory")
__device__ __forceinline__ void mbar_wait(uint32_t mbar, uint32_t parity) {
    asm volatile(
        "{\n\t"
        ".reg .pred P;\n\t"
        "WAIT_%=:\n\t"
        "mbarrier.try_wait.parity.acquire.cta.shared::cta.b64 P, [%0], %1, 0x989680;\n\t"
        "@P bra.uni DONE_%=;\n\t"
        "bra.uni WAIT_%=;\n\t"
        "DONE_%=:\n\t"
        "}" :: "r"(mbar), "r"(parity) : "memory");
}

__global__ void __launch_bounds__(256, 4)
k_fused(const float* __restrict__ enc,
        const int*   __restrict__ mask,
        const int*   __restrict__ heads,
        const int*   __restrict__ tails,
        const int*   __restrict__ labels,
        const float* __restrict__ wemb,
        const float* __restrict__ lemb,
        const float* __restrict__ clsw,   // [DD+16, 3]
        const float* __restrict__ clsb,   // [3]
        float*       __restrict__ out)    // logits [512*3] then loss [1]
{
    __shared__ __align__(128) unsigned char s_buf[NS][TBYTES];   // 32 KB
    __shared__ __align__(8)  unsigned long long s_mbar[NS];
    __shared__ float sred[8][3];
    __shared__ int   smsk[8];
    __shared__ int   s_last;

    const int span = blockIdx.x;         // 0..511
    const int b    = span >> 5;
    const int t    = threadIdx.x;        // 256 threads; thread t owns float4 lane t

    const int head  = heads[span];
    const int tail  = tails[span];
    const int start = head + 1;
    const int cnt   = tail - start;
    const int tiles = (cnt + TROWS - 1) / TROWS;

    const char* src0 = (const char*)enc + ((size_t)b * LL + start) * ROWB;
    const uint32_t mb0 = smem_u32(&s_mbar[0]);
    const uint32_t bf0 = smem_u32(&s_buf[0][0]);

    // ---- init barriers, issue prologue tiles ----
    if (t == 0) {
        MBAR_INIT(mb0, 1);
        MBAR_INIT(mb0 + 8, 1);
    }
    __syncthreads();
    if (t == 0) {
        #pragma unroll
        for (int tt = 0; tt < NS; ++tt) {
            if (tt < tiles) {
                const int rows = min(TROWS, cnt - tt * TROWS);
                const uint32_t bytes = rows * ROWB;
                const uint32_t mb = mb0 + (tt & 1) * 8;
                MBAR_EXPECT_TX(mb, bytes);
                BULK_G2S(bf0 + (tt & 1) * TBYTES, src0 + (size_t)tt * TBYTES, bytes, mb);
            }
        }
    }

    // ---- overlap: per-example mask length (L2-resident, 8 KB) ----
    int msum = 0;
    {
        const int* mrow = mask + (size_t)b * LL;
        #pragma unroll
        for (int i = 0; i < LL / 256; ++i) msum += mrow[t + i * 256];
    }

    // ---- consume tiles from smem ring ----
    float4 acc = make_float4(0.f, 0.f, 0.f, 0.f);
    for (int tt = 0; tt < tiles; ++tt) {
        const int st = tt & 1;
        mbar_wait(mb0 + st * 8, (tt >> 1) & 1);
        const int rows = min(TROWS, cnt - tt * TROWS);
        const float4* bp = (const float4*)&s_buf[st][0] + t;
        #pragma unroll
        for (int r = 0; r < TROWS; ++r) {
            if (r < rows) {
                float4 v = bp[r * ROWF];
                acc.x += v.x; acc.y += v.y; acc.z += v.z; acc.w += v.w;
            }
        }
        __syncthreads();   // all threads done reading stage st
        if (t == 0 && tt + NS < tiles) {
            const int nt   = tt + NS;
            const int rws  = min(TROWS, cnt - nt * TROWS);
            const uint32_t bytes = rws * ROWB;
            const uint32_t mb = mb0 + st * 8;
            MBAR_EXPECT_TX(mb, bytes);
            BULK_G2S(bf0 + st * TBYTES, src0 + (size_t)nt * TBYTES, bytes, mb);
        }
    }

    const float inv = 1.0f / (float)max(cnt, 1);
    acc.x *= inv; acc.y *= inv; acc.z *= inv; acc.w *= inv;

    // ---- fold this thread's 4 dims into 3 partial logits ----
    float p0, p1, p2;
    {
        const float* w = clsw + (size_t)(t * 4) * 3;   // coalesced, L2-resident
        p0 = acc.x * w[0] + acc.y * w[3] + acc.z * w[6] + acc.w * w[9];
        p1 = acc.x * w[1] + acc.y * w[4] + acc.z * w[7] + acc.w * w[10];
        p2 = acc.x * w[2] + acc.y * w[5] + acc.z * w[8] + acc.w * w[11];
    }

    // ---- block reduction of (p0, p1, p2, msum) ----
    #pragma unroll
    for (int o = 16; o; o >>= 1) {
        p0   += __shfl_down_sync(0xffffffffu, p0, o);
        p1   += __shfl_down_sync(0xffffffffu, p1, o);
        p2   += __shfl_down_sync(0xffffffffu, p2, o);
        msum += __shfl_down_sync(0xffffffffu, msum, o);
    }
    if ((t & 31) == 0) {
        sred[t >> 5][0] = p0; sred[t >> 5][1] = p1; sred[t >> 5][2] = p2;
        smsk[t >> 5] = msum;
    }
    __syncthreads();
    if (t == 0) {
        float l0 = 0.f, l1 = 0.f, l2 = 0.f; int len = 0;
        #pragma unroll
        for (int w = 0; w < 8; ++w) {
            l0 += sred[w][0]; l1 += sred[w][1]; l2 += sred[w][2]; len += smsk[w];
        }
        int wb = (tail - head) / WIDTH_BUCKET;
        wb = min(max(wb, 0), NUM_BUCKETS - 1);
        int lb = len / LEN_BUCKET;
        lb = min(max(lb, 0), NUM_BUCKETS - 1);

        float e0 = clsb[0], e1 = clsb[1], e2 = clsb[2];
        #pragma unroll
        for (int j = 0; j < 8; ++j) {
            const float wv = wemb[wb * 8 + j];
            const float lv = lemb[lb * 8 + j];
            const float* cw = clsw + (size_t)(DD + j) * 3;
            const float* cl = clsw + (size_t)(DD + 8 + j) * 3;
            e0 += wv * cw[0] + lv * cl[0];
            e1 += wv * cw[1] + lv * cl[1];
            e2 += wv * cw[2] + lv * cl[2];
        }
        float* o = out + (size_t)span * 3;
        o[0] = l0 + e0; o[1] = l1 + e1; o[2] = l2 + e2;
    }

    // ---- last-block-done: CE in-kernel ----
    __threadfence();
    if (t == 0) s_last = (atomicAdd(&g_done, 1u) == (unsigned)(NSPAN - 1));
    __syncthreads();
    if (!s_last) return;
    if (t == 0) g_done = 0;   // reset for next graph replay
    __threadfence();          // acquire: all blocks' logits visible

    float nll = 0.f;
    int valid = 0;
    #pragma unroll
    for (int k = 0; k < 2; ++k) {
        const int r = t + k * 256;        // 0..511
        const float a  = out[r * 3 + 0];
        const float b2 = out[r * 3 + 1];
        const float c  = out[r * 3 + 2];
        const float m = fmaxf(a, fmaxf(b2, c));
        const float lse = m + logf(expf(a - m) + expf(b2 - m) + expf(c - m));
        const int lab = labels[r];
        if (lab > -1) {
            valid += 1;
            const int cl = max(lab, 0);
            const float x = (cl == 0) ? a : ((cl == 1) ? b2 : c);
            nll += lse - x;
        }
    }
    #pragma unroll
    for (int o = 16; o; o >>= 1) {
        nll   += __shfl_down_sync(0xffffffffu, nll, o);
        valid += __shfl_down_sync(0xffffffffu, valid, o);
    }
    __shared__ float snll[8];
    __shared__ int   svld[8];
    if ((t & 31) == 0) { snll[t >> 5] = nll; svld[t >> 5] = valid; }
    __syncthreads();
    if (t == 0) {
        float tn = 0.f; int tv = 0;
        #pragma unroll
        for (int w = 0; w < 8; ++w) { tn += snll[w]; tv += svld[w]; }
        out[NSPAN * NUM_LABELS] = tn / (float)max(tv, 1);
    }
}

extern "C" void kernel_launch(void* const* d_in, const int* in_sizes, int n_in,
                              void* d_out, int out_size)
{
    const float* enc   = (const float*)d_in[0];  // [16,2048,1024] f32
    const int*   mask  = (const int*)  d_in[1];  // [16,2048] i32
    const int*   heads = (const int*)  d_in[2];  // [16,32] i32
    const int*   tails = (const int*)  d_in[3];  // [16,32] i32
    const int*   labs  = (const int*)  d_in[4];  // [16,32] i32
    const float* wemb  = (const float*)d_in[5];  // [64,8] f32
    const float* lemb  = (const float*)d_in[6];  // [64,8] f32
    const float* clsw  = (const float*)d_in[7];  // [1040,3] f32
    const float* clsb  = (const float*)d_in[8];  // [3] f32

    k_fused<<<NSPAN, 256>>>(enc, mask, heads, tails, labs,
                            wemb, lemb, clsw, clsb, (float*)d_out);
}